// round 16
// baseline (speedup 1.0000x reference)
#include <cuda_runtime.h>
#include <cstdint>

// CrossAttentionConditionInjection — analytic collapse, ONE kernel,
// TMA BULK weight loads (escape the LDG miss-slot ceiling).
//
// Math: K/V come from one condition token broadcast across seq => softmax
// weights are exactly 1/S (S=2048 pow2) => attn == v1 broadcast.
//   out[b,s,:] = Wo @ (Wv @ cond[b] + bv) + bo   (same vector for every s)
//
// R16 theory: every LDG arrangement saturates at ~750 GB/s because in-flight
// misses cap at ~8KB/SM (slot-tracked). cp.async.bulk in-flight bytes are
// bounded by issued copy size instead: 128 blocks x 64KB = 8MB outstanding.

#define BDIM 1024
#define NB   2
#define NS   2048
#define GRID 128            // 1 block/SM -> co-resident, barrier-safe
#define TPB  1024
#define CHUNK_BYTES (8 * BDIM * 4)          // 8 rows x 4KB = 32KB
#define SMEM_BYTES  (2 * CHUNK_BYTES)       // Wv chunk + Wo chunk = 64KB

__device__ float    g_v1[NB * BDIM];
__device__ unsigned g_bar = 0;              // monotonic ticket ctr (replay-safe)

__device__ __forceinline__ void grid_sync() {
    __syncthreads();
    if (threadIdx.x == 0) {
        __threadfence();
        unsigned ticket = atomicAdd(&g_bar, 1u);
        unsigned target = (ticket / GRID + 1u) * GRID;
        while (atomicAdd(&g_bar, 0u) < target)
            __nanosleep(32);
        __threadfence();
    }
    __syncthreads();
}

__device__ __forceinline__ void mbar_init(uint32_t mbar, uint32_t cnt) {
    asm volatile("mbarrier.init.shared.b64 [%0], %1;" :: "r"(mbar), "r"(cnt)
                 : "memory");
}
__device__ __forceinline__ void mbar_expect_tx(uint32_t mbar, uint32_t bytes) {
    asm volatile("mbarrier.arrive.expect_tx.shared.b64 _, [%0], %1;"
                 :: "r"(mbar), "r"(bytes) : "memory");
}
__device__ __forceinline__ void bulk_g2s(uint32_t dst_smem, const void* src,
                                         uint32_t bytes, uint32_t mbar) {
    asm volatile(
        "cp.async.bulk.shared::cta.global.mbarrier::complete_tx::bytes "
        "[%0], [%1], %2, [%3];"
        :: "r"(dst_smem), "l"(src), "r"(bytes), "r"(mbar) : "memory");
}
__device__ __forceinline__ void mbar_wait_parity0(uint32_t mbar) {
    uint32_t done;
    do {
        asm volatile(
            "{\n\t.reg .pred p;\n\t"
            "mbarrier.try_wait.parity.acquire.cta.shared::cta.b64 p, [%1], 0, 0x989680;\n\t"
            "selp.b32 %0, 1, 0, p;\n\t}"
            : "=r"(done) : "r"(mbar) : "memory");
    } while (!done);
}

__global__ void __launch_bounds__(TPB, 1)
fused_kernel(const float* __restrict__ Wv, const float* __restrict__ cond,
             const float* __restrict__ bv, const float* __restrict__ Wo,
             const float* __restrict__ bo, float4* __restrict__ out) {
    extern __shared__ float4 s_w[];          // [16][256]: rows 0-7 Wv, 8-15 Wo
    __shared__ float    s_o1[16];
    __shared__ uint64_t s_mbar;

    const int warp = threadIdx.x >> 5;
    const int lane = threadIdx.x & 31;
    const int r0   = blockIdx.x * 8;         // this block's 8 rows of each W

    const uint32_t mbar = (uint32_t)__cvta_generic_to_shared(&s_mbar);
    const uint32_t sdat = (uint32_t)__cvta_generic_to_shared(s_w);

    // ---- Phase 1: two 32KB TMA bulk copies; 8MB in flight chip-wide ----
    if (threadIdx.x == 0) mbar_init(mbar, 1);
    __syncthreads();
    if (threadIdx.x == 0) {
        mbar_expect_tx(mbar, SMEM_BYTES);
        bulk_g2s(sdat,               Wv + (size_t)r0 * BDIM, CHUNK_BYTES, mbar);
        bulk_g2s(sdat + CHUNK_BYTES, Wo + (size_t)r0 * BDIM, CHUNK_BYTES, mbar);
    }
    mbar_wait_parity0(mbar);                 // all 1024 threads

    // ---- Phase 2: v1 dots from smem Wv + L2-hot cond ----
    if (warp < 16) {
        int rl = warp >> 1;                  // 0..7
        int b  = warp & 1;
        const float4* w4 = s_w + rl * 256;
        const float4* x4 = reinterpret_cast<const float4*>(cond + (size_t)b * BDIM);
        float sum = 0.f;
#pragma unroll
        for (int i = 0; i < 8; ++i) {
            float4 wv = w4[lane + i * 32];
            float4 xv = x4[lane + i * 32];
            sum += wv.x * xv.x + wv.y * xv.y + wv.z * xv.z + wv.w * xv.w;
        }
#pragma unroll
        for (int off = 16; off; off >>= 1)
            sum += __shfl_xor_sync(0xffffffffu, sum, off);
        if (lane == 0)
            g_v1[b * BDIM + r0 + rl] = sum + bv[r0 + rl];
    }

    grid_sync();                             // all 2048 v1 values published

    // ---- Phase 3: o1 dots from smem Wo + 8KB global v1 ----
    if (warp < 16) {
        int rl = warp >> 1;
        int b  = warp & 1;
        const float4* w4 = s_w + (8 + rl) * 256;
        const float4* v4 = reinterpret_cast<const float4*>(g_v1 + (size_t)b * BDIM);
        float sum = 0.f;
#pragma unroll
        for (int i = 0; i < 8; ++i) {
            float4 wv = w4[lane + i * 32];
            float4 xv = v4[lane + i * 32];
            sum += wv.x * xv.x + wv.y * xv.y + wv.z * xv.z + wv.w * xv.w;
        }
#pragma unroll
        for (int off = 16; off; off >>= 1)
            sum += __shfl_xor_sync(0xffffffffu, sum, off);
        if (lane == 0) s_o1[b * 8 + rl] = sum + bo[r0 + rl];
    }
    __syncthreads();

    // ---- Phase 4: broadcast block's 32B chunk x 2 batches over all s ----
    // (validated in R13/R14): 8192 (c,s,b) tuples, 8 per thread.
    const float4* o14 = reinterpret_cast<const float4*>(s_o1);
    float4 q0 = o14[0], q1 = o14[1], q2 = o14[2], q3 = o14[3];
    const int dbase = r0 >> 2;
#pragma unroll
    for (int k = 0; k < 8; ++k) {
        int i = k * TPB + threadIdx.x;
        int c = i & 1;
        int s = (i >> 1) & (NS - 1);
        int b = i >> 12;
        float4 val = (b == 0) ? (c == 0 ? q0 : q1) : (c == 0 ? q2 : q3);
        size_t addr = (size_t)b * NS * (BDIM / 4) + (size_t)s * (BDIM / 4)
                    + dbase + c;
        __stcs(out + addr, val);
    }
}

extern "C" void kernel_launch(void* const* d_in, const int* in_sizes, int n_in,
                              void* d_out, int out_size) {
    // metadata order: hidden_states, condition, Wq, bq, Wk, bk, Wv, bv, Wo, bo
    const float* cond = (const float*)d_in[1];
    const float* Wv   = (const float*)d_in[6];
    const float* bv   = (const float*)d_in[7];
    const float* Wo   = (const float*)d_in[8];
    const float* bo   = (const float*)d_in[9];

    static int attr_done = 0;                // idempotent 64KB dyn-smem opt-in
    if (!attr_done) {
        cudaFuncSetAttribute(fused_kernel,
                             cudaFuncAttributeMaxDynamicSharedMemorySize,
                             SMEM_BYTES);
        attr_done = 1;
    }
    fused_kernel<<<GRID, TPB, SMEM_BYTES>>>(Wv, cond, bv, Wo, bo,
                                            (float4*)d_out);
}